// round 7
// baseline (speedup 1.0000x reference)
#include <cuda_runtime.h>
#include <math.h>

#define HW 64
#define NP 4096
#define MAXB 32

// per-block partial sums + monotonic ticket (never reset; graph-replay-safe)
__device__ float g_part[MAXB * 8];
__device__ unsigned int g_tick;

// 256-thread subgroup barrier (ids 1..4)
__device__ __forceinline__ void group_bar(int t) {
    asm volatile("bar.sync %0, 256;" :: "r"((t >> 8) + 1) : "memory");
}

__device__ __forceinline__ void ce(float& a, float& b, bool up) {
    float lo = fminf(a, b), hi = fmaxf(a, b);
    a = up ? lo : hi;
    b = up ? hi : lo;
}

__global__ __launch_bounds__(1024, 1)
void chamfer_kernel(const float* __restrict__ depth,
                    const float* __restrict__ bnd,
                    float* __restrict__ out,
                    float inv_total, int nblk) {
    __shared__ float sm[2 * NP];   // double-buffered exchange; sm+NP holds final sorted target
    __shared__ float swarp[32];
    const int t   = threadIdx.x;
    const int blk = blockIdx.x;
    const int h   = blk & 3;          // query quarter
    const int dir = (blk >> 2) & 1;   // 0: queries=sobel,target=bnd ; 1: queries=bnd,target=sobel
    const int b   = blk >> 3;

    const float* dpt = depth + b * NP;
    const float* bb  = bnd   + b * NP;

    // ---- Phase 1: one query per thread (registers) ----
    const int e = h * 1024 + t;
    float q;
    if (dir == 0) {
        int y = e >> 6, x = e & 63;
        float p[3][3];
        #pragma unroll
        for (int dy = -1; dy <= 1; dy++)
            #pragma unroll
            for (int dx = -1; dx <= 1; dx++) {
                int yy = y + dy, xx = x + dx;
                bool ok = (yy >= 0) & (yy < HW) & (xx >= 0) & (xx < HW);
                p[dy + 1][dx + 1] = ok ? dpt[yy * HW + xx] : 0.0f;
            }
        float gx = (p[0][0] - p[0][2]) + 2.0f * (p[1][0] - p[1][2]) + (p[2][0] - p[2][2]);
        float gy = (p[0][0] - p[2][0]) + 2.0f * (p[0][1] - p[2][1]) + (p[0][2] - p[2][2]);
        q = sqrtf(gx * gx + gy * gy + 1e-8f);
    } else {
        q = bb[e];
    }

    // ---- Phase 2: build full 4096 target, 4 elems/thread ----
    const int idx = 4 * t;
    float w[4];
    if (dir == 0) {
        float4 v = *(const float4*)(bb + idx);
        w[0] = v.x; w[1] = v.y; w[2] = v.z; w[3] = v.w;
    } else {
        int y = idx >> 6, x0 = idx & 63;   // x0 multiple of 4
        float p[3][6];                     // rows y-1..y+1, cols x0-1..x0+4
        #pragma unroll
        for (int ry = 0; ry < 3; ry++) {
            int yy = y + ry - 1;
            bool yok = (yy >= 0) & (yy < HW);
            #pragma unroll
            for (int cx = 0; cx < 6; cx++) {
                int xx = x0 + cx - 1;
                bool ok = yok & (xx >= 0) & (xx < HW);
                p[ry][cx] = ok ? dpt[yy * HW + xx] : 0.0f;
            }
        }
        #pragma unroll
        for (int m = 0; m < 4; m++) {
            float gx = (p[0][m] - p[0][m + 2]) + 2.0f * (p[1][m] - p[1][m + 2]) + (p[2][m] - p[2][m + 2]);
            float gy = (p[0][m] + 2.0f * p[0][m + 1] + p[0][m + 2])
                     - (p[2][m] + 2.0f * p[2][m + 1] + p[2][m + 2]);
            w[m] = sqrtf(gx * gx + gy * gy + 1e-8f);
        }
    }

    // ---- Phase 3: ascending bitonic sort of 4096, 4 elems/thread ----
    // j>=128: double-buffered smem, 1 barrier/step (full sync iff k>=2048 && j>=512,
    // from barrier-span analysis: span must cover max(j, j_prev)/4 threads).
    // j=4..64: shfl (lane distance j/4). j=2,1: in-thread.
    int pbuf = 0;
    #pragma unroll
    for (int k = 2; k <= NP; k <<= 1) {
        #pragma unroll
        for (int j = k >> 1; j >= 1; j >>= 1) {
            if (j >= 128) {
                float* buf = sm + pbuf * NP;
                *(float4*)&buf[idx] = make_float4(w[0], w[1], w[2], w[3]);
                if (k >= 2048 && j >= 512) __syncthreads(); else group_bar(t);
                bool keepMin = ((idx & j) == 0) == ((idx & k) == 0);
                float4 o = *(float4*)&buf[idx ^ j];
                w[0] = keepMin ? fminf(w[0], o.x) : fmaxf(w[0], o.x);
                w[1] = keepMin ? fminf(w[1], o.y) : fmaxf(w[1], o.y);
                w[2] = keepMin ? fminf(w[2], o.z) : fmaxf(w[2], o.z);
                w[3] = keepMin ? fminf(w[3], o.w) : fmaxf(w[3], o.w);
                pbuf ^= 1;
            } else if (j >= 4) {
                bool keepMin = ((idx & j) == 0) == ((idx & k) == 0);
                #pragma unroll
                for (int m = 0; m < 4; m++) {
                    float o = __shfl_xor_sync(0xffffffffu, w[m], j >> 2);
                    w[m] = keepMin ? fminf(w[m], o) : fmaxf(w[m], o);
                }
            } else if (j == 2) {             // k >= 4 here; same dir for all 4 elems
                bool up = ((idx & k) == 0);
                ce(w[0], w[2], up);
                ce(w[1], w[3], up);
            } else {                          // j == 1
                if (k == 2) {                 // dirs differ between the two pairs
                    ce(w[0], w[1], true);
                    ce(w[2], w[3], false);
                } else {
                    bool up = ((idx & k) == 0);
                    ce(w[0], w[1], up);
                    ce(w[2], w[3], up);
                }
            }
        }
    }

    // Final sorted target -> sm+NP (buf1: its last reads were at j=256 step,
    // distance 64 threads, already covered by the j=128 group bar). Then full sync.
    float* sT = sm + NP;
    *(float4*)&sT[idx] = make_float4(w[0], w[1], w[2], w[3]);
    __syncthreads();

    // ---- Phase 4: 12-level branchless search (saturates at NP-1) ----
    float x = q;
    int pos = 0;
    #pragma unroll
    for (int s = NP / 2; s >= 1; s >>= 1) {
        if (sT[pos + s - 1] < x) pos += s;
    }
    // if x > all elements: pos=NP-1 and sT[pos]<x; fabsf gives distance to max.
    float acc = fabsf(sT[pos] - x);
    if (pos > 0) acc = fminf(acc, x - sT[pos - 1]);

    // ---- Phase 5: block reduce, partial publish, last-block finalize ----
    #pragma unroll
    for (int o = 16; o > 0; o >>= 1) acc += __shfl_xor_sync(0xffffffffu, acc, o);
    if ((t & 31) == 0) swarp[t >> 5] = acc;
    __syncthreads();
    if (t < 32) {
        float z = swarp[t];            // exactly 32 warps
        #pragma unroll
        for (int o = 16; o > 0; o >>= 1) z += __shfl_xor_sync(0xffffffffu, z, o);
        if (t == 0) {
            g_part[blk] = z;
            __threadfence();
            unsigned int tk = atomicAdd(&g_tick, 1u);
            if ((tk % (unsigned)nblk) == (unsigned)(nblk - 1)) {
                __threadfence();       // acquire: all partials of this launch visible
                float s = 0.0f;
                for (int i2 = 0; i2 < nblk; i2++)
                    s += ((volatile float*)g_part)[i2];
                out[0] = s * inv_total;   // plain store; overwrites poison each replay
            }
        }
    }
}

extern "C" void kernel_launch(void* const* d_in, const int* in_sizes, int n_in,
                              void* d_out, int out_size) {
    const float* depth = (const float*)d_in[0];
    const float* bnd   = (const float*)d_in[1];
    float* out = (float*)d_out;

    int B = in_sizes[0] / NP;
    if (B > MAXB) B = MAXB;
    int nblk = B * 8;
    float inv_total = 1.0f / (float)(B * NP);

    chamfer_kernel<<<nblk, 1024>>>(depth, bnd, out, inv_total, nblk);
}

// round 10
// speedup vs baseline: 1.8052x; 1.8052x over previous
#include <cuda_runtime.h>
#include <math.h>

#define HW 64
#define NP 4096
#define CK 1024
#define MAXB 32

// scratch: [batch][arr(0=g,1=bnd)][4096] — four sorted ascending 1024-chunks per array
__device__ __align__(16) float g_scr[2 * MAXB * NP];
// monotonically-increasing grid-barrier ticket counter (never reset; graph-replay-safe)
__device__ unsigned int g_bar;

__global__ __launch_bounds__(1024, 1)
void chamfer_kernel(const float* __restrict__ depth,
                    const float* __restrict__ bnd,
                    float* __restrict__ out,
                    float inv_total) {
    __shared__ float sm[NP];       // sort: dbuf = sm[0..2047]; query: full 4096 target
    __shared__ float swarp[32];
    const int t   = threadIdx.x;
    const int blk = blockIdx.x;
    const int c   = blk & 3;          // chunk quarter
    const int arr = (blk >> 2) & 1;   // 0 = sobel(g), 1 = boundary
    const int b   = blk >> 3;         // batch
    const unsigned int nblk = gridDim.x;

    if (blk == 0 && t == 0) out[0] = 0.0f;   // adds happen only after grid barrier

    // ---- Phase 1: one element per thread ----
    const int e = c * CK + t;
    float v;
    if (arr == 1) {
        v = bnd[b * NP + e];
    } else {
        const float* d = depth + b * NP;
        int y = e >> 6, x = e & 63;
        float p[3][3];
        #pragma unroll
        for (int dy = -1; dy <= 1; dy++)
            #pragma unroll
            for (int dx = -1; dx <= 1; dx++) {
                int yy = y + dy, xx = x + dx;
                bool ok = (yy >= 0) & (yy < HW) & (xx >= 0) & (xx < HW);
                p[dy + 1][dx + 1] = ok ? d[yy * HW + xx] : 0.0f;
            }
        float gx = (p[0][0] - p[0][2]) + 2.0f * (p[1][0] - p[1][2]) + (p[2][0] - p[2][2]);
        float gy = (p[0][0] - p[2][0]) + 2.0f * (p[0][1] - p[2][1]) + (p[0][2] - p[2][2]);
        v = sqrtf(gx * gx + gy * gy + 1e-8f);
    }

    // ---- Phase 2: ascending bitonic sort of 1024 elems, 1 elem/thread ----
    // j<=16: shfl (within-warp; lane distance j). j>=32: double-buffered smem
    // with ONE full __syncthreads per step (j=32 crosses warps — shfl CANNOT
    // do it; this was the R8/R9 bug). 15 smem steps total.
    int pbuf = 0;
    #pragma unroll
    for (int k = 2; k <= CK; k <<= 1) {
        #pragma unroll
        for (int j = k >> 1; j >= 1; j >>= 1) {
            bool keepMin = ((t & j) == 0) == ((t & k) == 0);
            float o;
            if (j >= 32) {
                float* buf = sm + pbuf * CK;
                buf[t] = v;
                __syncthreads();
                o = buf[t ^ j];
                pbuf ^= 1;
            } else {
                o = __shfl_xor_sync(0xffffffffu, v, j);
            }
            v = keepMin ? fminf(v, o) : fmaxf(v, o);
        }
    }

    // publish sorted chunk (v stays in register as this thread's query;
    // queries form the same multiset; the final sum is permutation-invariant)
    g_scr[(b * 2 + arr) * NP + e] = v;

    // ---- Phase 3: grid barrier (ticket-based, replay-safe) ----
    __syncthreads();   // covers last smem reads before phase-4 overwrite
    if (t == 0) {
        __threadfence();
        unsigned int ticket = atomicAdd(&g_bar, 1u);
        unsigned int target = (ticket / nblk + 1u) * nblk;
        while (*(volatile unsigned int*)&g_bar < target) { }
    }
    __syncthreads();
    __threadfence();

    // ---- Phase 4: load other array's 4 sorted chunks, search (4-way ILP) ----
    const float* tgt = g_scr + (b * 2 + (arr ^ 1)) * NP;
    ((float4*)sm)[t] = ((const float4*)tgt)[t];   // 4096 floats
    __syncthreads();

    const float x = v;
    float dmin = 3.4e38f;
    #pragma unroll
    for (int ch = 0; ch < 4; ch++) {
        const float* T = sm + (ch << 10);
        int pos = 0;                  // branchless lower_bound, saturates at CK-1
        #pragma unroll
        for (int s = CK / 2; s >= 1; s >>= 1) {
            if (T[pos + s - 1] < x) pos += s;
        }
        // if x > all elements of chunk: pos=CK-1, T[pos]<x, fabsf = dist to chunk max
        float dd = fabsf(T[pos] - x);
        if (pos > 0) dd = fminf(dd, x - T[pos - 1]);
        dmin = fminf(dmin, dd);
    }
    float acc = dmin;

    // ---- Phase 5: reduce + accumulate ----
    #pragma unroll
    for (int o = 16; o > 0; o >>= 1) acc += __shfl_xor_sync(0xffffffffu, acc, o);
    if ((t & 31) == 0) swarp[t >> 5] = acc;
    __syncthreads();
    if (t < 32) {
        float z = swarp[t];           // exactly 32 warps
        #pragma unroll
        for (int o = 16; o > 0; o >>= 1) z += __shfl_xor_sync(0xffffffffu, z, o);
        if (t == 0) atomicAdd(out, z * inv_total);
    }
}

extern "C" void kernel_launch(void* const* d_in, const int* in_sizes, int n_in,
                              void* d_out, int out_size) {
    const float* depth = (const float*)d_in[0];
    const float* bnd   = (const float*)d_in[1];
    float* out = (float*)d_out;

    int B = in_sizes[0] / NP;
    if (B > MAXB) B = MAXB;
    float inv_total = 1.0f / (float)(B * NP);

    chamfer_kernel<<<B * 8, 1024>>>(depth, bnd, out, inv_total);
}

// round 11
// speedup vs baseline: 1.8482x; 1.0238x over previous
#include <cuda_runtime.h>
#include <cooperative_groups.h>
#include <math.h>

namespace cg = cooperative_groups;

#define HW 64
#define NP 4096
#define CK 1024
#define MAXB 32

// per-block partial sums + monotonic ticket (never reset; graph-replay-safe)
__device__ float g_part[MAXB * 8];
__device__ unsigned int g_tick;

__global__ __launch_bounds__(1024, 1) __cluster_dims__(8, 1, 1)
void chamfer_kernel(const float* __restrict__ depth,
                    const float* __restrict__ bnd,
                    float* __restrict__ out,
                    float inv_total, int nblk) {
    __shared__ float sm[NP];          // sort dbuf (first 2048); then search target
    __shared__ float s_sorted[CK];    // this block's sorted chunk (DSMEM-visible)
    __shared__ float swarp[32];

    cg::cluster_group cluster = cg::this_cluster();
    const int t    = threadIdx.x;
    const int blk  = blockIdx.x;
    const int rank = (int)cluster.block_rank();   // 0..7 within (arr, chunk)
    const int c    = rank & 3;            // chunk quarter
    const int arr  = rank >> 2;           // 0 = sobel(g), 1 = boundary
    const int b    = blk >> 3;            // batch

    // ---- Phase 1: one element per thread ----
    const int e = c * CK + t;
    float v;
    if (arr == 1) {
        v = bnd[b * NP + e];
    } else {
        const float* d = depth + b * NP;
        int y = e >> 6, x = e & 63;
        float p[3][3];
        #pragma unroll
        for (int dy = -1; dy <= 1; dy++)
            #pragma unroll
            for (int dx = -1; dx <= 1; dx++) {
                int yy = y + dy, xx = x + dx;
                bool ok = (yy >= 0) & (yy < HW) & (xx >= 0) & (xx < HW);
                p[dy + 1][dx + 1] = ok ? d[yy * HW + xx] : 0.0f;
            }
        float gx = (p[0][0] - p[0][2]) + 2.0f * (p[1][0] - p[1][2]) + (p[2][0] - p[2][2]);
        float gy = (p[0][0] - p[2][0]) + 2.0f * (p[0][1] - p[2][1]) + (p[0][2] - p[2][2]);
        v = sqrtf(gx * gx + gy * gy + 1e-8f);
    }

    // ---- Phase 2: ascending bitonic sort of 1024 elems, 1 elem/thread ----
    // j<=16: shfl (in-warp). j>=32: double-buffered smem, one __syncthreads per
    // step (j=32 crosses warps — never shfl it; R8/R9 lesson). 15 smem steps.
    int pbuf = 0;
    #pragma unroll
    for (int k = 2; k <= CK; k <<= 1) {
        #pragma unroll
        for (int j = k >> 1; j >= 1; j >>= 1) {
            bool keepMin = ((t & j) == 0) == ((t & k) == 0);
            float o;
            if (j >= 32) {
                float* buf = sm + pbuf * CK;
                buf[t] = v;
                __syncthreads();
                o = buf[t ^ j];
                pbuf ^= 1;
            } else {
                o = __shfl_xor_sync(0xffffffffu, v, j);
            }
            v = keepMin ? fminf(v, o) : fmaxf(v, o);
        }
    }

    // publish sorted chunk into cluster-visible smem (v stays as this thread's query)
    s_sorted[t] = v;

    // ---- Phase 3: cluster barrier (orders smem writes for DSMEM readers) ----
    cluster.sync();

    // ---- Phase 4: pull the OTHER array's 4 sorted chunks from peer CTAs ----
    // thread t copies one float4 from peer rank (arr^1)*4 + (t>>8)
    {
        int ch = t >> 8;                    // 0..3
        int off = (t & 255) * 4;            // float4-aligned offset within chunk
        const float* peer = cluster.map_shared_rank(s_sorted, (arr ^ 1) * 4 + ch);
        float4 q = *(const float4*)(peer + off);
        *(float4*)(sm + (ch << 10) + off) = q;
    }
    // all DSMEM reads done before any CTA may exit / proceed
    cluster.sync();

    // ---- Phase 5: 4-chunk search, 10 levels each, 4-way ILP ----
    const float x = v;
    float dmin = 3.4e38f;
    #pragma unroll
    for (int ch = 0; ch < 4; ch++) {
        const float* T = sm + (ch << 10);
        int pos = 0;                  // branchless lower_bound, saturates at CK-1
        #pragma unroll
        for (int s = CK / 2; s >= 1; s >>= 1) {
            if (T[pos + s - 1] < x) pos += s;
        }
        // if x > all of chunk: pos=CK-1, T[pos]<x, fabsf = dist to chunk max
        float dd = fabsf(T[pos] - x);
        if (pos > 0) dd = fminf(dd, x - T[pos - 1]);
        dmin = fminf(dmin, dd);
    }
    float acc = dmin;

    // ---- Phase 6: block reduce; ticket finalize (replay-safe, race-free) ----
    #pragma unroll
    for (int o = 16; o > 0; o >>= 1) acc += __shfl_xor_sync(0xffffffffu, acc, o);
    if ((t & 31) == 0) swarp[t >> 5] = acc;
    __syncthreads();
    if (t < 32) {
        float z = swarp[t];           // exactly 32 warps
        #pragma unroll
        for (int o = 16; o > 0; o >>= 1) z += __shfl_xor_sync(0xffffffffu, z, o);
        if (t == 0) {
            g_part[blk] = z;
            __threadfence();
            unsigned int tk = atomicAdd(&g_tick, 1u);
            if ((tk % (unsigned)nblk) == (unsigned)(nblk - 1)) {
                __threadfence();      // all partials of this launch visible
                float s = 0.0f;
                for (int i2 = 0; i2 < nblk; i2++)
                    s += ((volatile float*)g_part)[i2];
                out[0] = s * inv_total;   // overwrites poison on every replay
            }
        }
    }
}

extern "C" void kernel_launch(void* const* d_in, const int* in_sizes, int n_in,
                              void* d_out, int out_size) {
    const float* depth = (const float*)d_in[0];
    const float* bnd   = (const float*)d_in[1];
    float* out = (float*)d_out;

    int B = in_sizes[0] / NP;
    if (B > MAXB) B = MAXB;
    int nblk = B * 8;                 // always a multiple of the cluster size 8
    float inv_total = 1.0f / (float)(B * NP);

    chamfer_kernel<<<nblk, 1024>>>(depth, bnd, out, inv_total, nblk);
}